// round 1
// baseline (speedup 1.0000x reference)
#include <cuda_runtime.h>

// Problem constants
#define TT   8192           // tokens = B*S
#define HH   2048           // hidden
#define II   4096           // intermediate
#define EE   8              // experts
#define TK   (TT*2)         // dispatched rows (top-2)
#define BM   128
#define BN   128
#define BKD  16
#define MAXTILES 144        // worst case: 128 full tiles + 7 remainders

// Scratch (device globals: allocation-free rule)
__device__ float g_h[(size_t)TK * II];      // 256 MB: GEMM1 output
__device__ float g_out[(size_t)TK * HH];    // 128 MB: GEMM2 output (weighted)
__device__ int   g_topi[TK];
__device__ float g_topw[TK];
__device__ int   g_rowtok[TK];
__device__ float g_rw[TK];
__device__ int   g_pos[TK];
__device__ int   g_counts[EE];
__device__ int   g_offsets[EE + 1];
__device__ int   g_fill[EE];
__device__ int   g_tile_e[MAXTILES];
__device__ int   g_tile_row[MAXTILES];
__device__ int   g_tile_rows[MAXTILES];
__device__ int   g_num_tiles;

// ---------------------------------------------------------------------------
__global__ void init_kernel() {
    int t = threadIdx.x;
    if (t < EE) { g_counts[t] = 0; g_fill[t] = 0; }
    if (t == 0) g_num_tiles = 0;
}

// ---------------------------------------------------------------------------
// Router: one warp per token. 8 expert dots over H=2048, fp32 softmax, top-2.
__global__ void router_kernel(const float* __restrict__ x,
                              const float* __restrict__ rw) {
    int warp = (blockIdx.x * blockDim.x + threadIdx.x) >> 5;
    int lane = threadIdx.x & 31;
    if (warp >= TT) return;
    const float* xr = x + (size_t)warp * HH;
    float acc[EE];
#pragma unroll
    for (int e = 0; e < EE; e++) acc[e] = 0.f;
    for (int i = lane * 4; i < HH; i += 128) {
        float4 xv = *(const float4*)&xr[i];
#pragma unroll
        for (int e = 0; e < EE; e++) {
            float4 wv = *(const float4*)&rw[e * HH + i];
            acc[e] += xv.x * wv.x + xv.y * wv.y + xv.z * wv.z + xv.w * wv.w;
        }
    }
#pragma unroll
    for (int e = 0; e < EE; e++)
#pragma unroll
        for (int off = 16; off; off >>= 1)
            acc[e] += __shfl_xor_sync(0xffffffffu, acc[e], off);

    if (lane == 0) {
        float mx = acc[0];
#pragma unroll
        for (int e = 1; e < EE; e++) mx = fmaxf(mx, acc[e]);
        float p[EE], s = 0.f;
#pragma unroll
        for (int e = 0; e < EE; e++) { p[e] = expf(acc[e] - mx); s += p[e]; }
        float inv = 1.f / s;
        int i1 = 0; float v1 = p[0];
#pragma unroll
        for (int e = 1; e < EE; e++) if (p[e] > v1) { v1 = p[e]; i1 = e; }
        int i2 = -1; float v2 = -1.f;
#pragma unroll
        for (int e = 0; e < EE; e++)
            if (e != i1 && p[e] > v2) { v2 = p[e]; i2 = e; }
        g_topi[warp * 2]     = i1; g_topw[warp * 2]     = v1 * inv;
        g_topi[warp * 2 + 1] = i2; g_topw[warp * 2 + 1] = v2 * inv;
        atomicAdd(&g_counts[i1], 1);
        atomicAdd(&g_counts[i2], 1);
    }
}

// ---------------------------------------------------------------------------
// Offsets + tile metadata (tiny serial work). Also writes tokens_per_expert
// tail of d_out if out_size > T*H, and zero-fills any remaining tail.
__global__ void build_kernel(float* d_out, long long out_size) {
    if (threadIdx.x != 0) return;
    int off = 0;
    for (int e = 0; e < EE; e++) { g_offsets[e] = off; off += g_counts[e]; }
    g_offsets[EE] = off;
    int nt = 0;
    for (int e = 0; e < EE; e++) {
        int n = g_counts[e];
        for (int j = 0; j < n; j += BM) {
            g_tile_e[nt]    = e;
            g_tile_row[nt]  = g_offsets[e] + j;
            g_tile_rows[nt] = (n - j < BM) ? (n - j) : BM;
            nt++;
        }
    }
    g_num_tiles = nt;
    long long base = (long long)TT * HH;
    long long extra = out_size - base;
    for (long long i = 0; i < extra; i++)
        d_out[base + i] = (i < EE) ? (float)g_counts[i] : 0.f;
}

// ---------------------------------------------------------------------------
// Scatter dispatched rows into expert-sorted order (unstable within expert;
// valid because final combine is an order-independent per-token sum).
__global__ void scatter_kernel() {
    int i = blockIdx.x * blockDim.x + threadIdx.x;
    if (i >= TK) return;
    int e = g_topi[i];
    int p = g_offsets[e] + atomicAdd(&g_fill[e], 1);
    g_rowtok[p] = i >> 1;
    g_rw[p]     = g_topw[i];
    g_pos[i]    = p;
}

// ---------------------------------------------------------------------------
// GEMM1: h[r, :] = gelu_tanh( x[tok(r), :] @ w1[e]  )   [gathered A rows]
__global__ __launch_bounds__(256, 2)
void gemm1_kernel(const float* __restrict__ X, const float* __restrict__ W1) {
    int tile = blockIdx.y;
    if (tile >= g_num_tiles) return;
    const int e    = g_tile_e[tile];
    const int row0 = g_tile_row[tile];
    const int rows = g_tile_rows[tile];
    const int n0   = blockIdx.x * BN;
    const float* __restrict__ Bp = W1 + (size_t)e * HH * II;

    __shared__ float As[BKD][BM + 4];
    __shared__ float Bs[BKD][BN];
    __shared__ int   stok[BM];

    const int tid = threadIdx.x;
    if (tid < BM) {
        int mm = (tid < rows) ? tid : (rows - 1);
        stok[tid] = g_rowtok[row0 + mm];
    }
    __syncthreads();

    const int tx = tid & 15, ty = tid >> 4;
    float acc[8][8];
#pragma unroll
    for (int i = 0; i < 8; i++)
#pragma unroll
        for (int j = 0; j < 8; j++) acc[i][j] = 0.f;

    for (int k0 = 0; k0 < HH; k0 += BKD) {
#pragma unroll
        for (int l = 0; l < 2; l++) {
            int idx = tid + l * 256;
            int m = idx >> 2, c4 = (idx & 3) * 4;
            float4 v = *(const float4*)&X[(size_t)stok[m] * HH + k0 + c4];
            As[c4 + 0][m] = v.x; As[c4 + 1][m] = v.y;
            As[c4 + 2][m] = v.z; As[c4 + 3][m] = v.w;
        }
#pragma unroll
        for (int l = 0; l < 2; l++) {
            int idx = tid + l * 256;
            int kk = idx >> 5, n4 = (idx & 31) * 4;
            *(float4*)&Bs[kk][n4] =
                *(const float4*)&Bp[(size_t)(k0 + kk) * II + n0 + n4];
        }
        __syncthreads();
#pragma unroll
        for (int kk = 0; kk < BKD; kk++) {
            float a[8], b[8];
#pragma unroll
            for (int i = 0; i < 4; i++) {
                a[i]     = As[kk][ty * 4 + i];
                a[4 + i] = As[kk][64 + ty * 4 + i];
            }
#pragma unroll
            for (int j = 0; j < 4; j++) {
                b[j]     = Bs[kk][tx * 4 + j];
                b[4 + j] = Bs[kk][64 + tx * 4 + j];
            }
#pragma unroll
            for (int i = 0; i < 8; i++)
#pragma unroll
                for (int j = 0; j < 8; j++)
                    acc[i][j] = fmaf(a[i], b[j], acc[i][j]);
        }
        __syncthreads();
    }

    // epilogue: tanh-GELU + store
#pragma unroll
    for (int i = 0; i < 8; i++) {
        int m = (i < 4) ? (ty * 4 + i) : (64 + ty * 4 + i - 4);
        if (m >= rows) continue;
        size_t base = (size_t)(row0 + m) * II + n0;
#pragma unroll
        for (int jh = 0; jh < 2; jh++) {
            float4 v;
            float* pv = &v.x;
#pragma unroll
            for (int j = 0; j < 4; j++) {
                float z = acc[i][jh * 4 + j];
                float t = 0.7978845608028654f * (z + 0.044715f * z * z * z);
                pv[j] = 0.5f * z * (1.f + tanhf(t));
            }
            *(float4*)&g_h[base + (jh == 0 ? tx * 4 : 64 + tx * 4)] = v;
        }
    }
}

// ---------------------------------------------------------------------------
// GEMM2: out[r, :] = rw[r] * ( h[r, :] @ w2[e] )
__global__ __launch_bounds__(256, 2)
void gemm2_kernel(const float* __restrict__ W2) {
    int tile = blockIdx.y;
    if (tile >= g_num_tiles) return;
    const int e    = g_tile_e[tile];
    const int row0 = g_tile_row[tile];
    const int rows = g_tile_rows[tile];
    const int n0   = blockIdx.x * BN;
    const float* __restrict__ Bp = W2 + (size_t)e * II * HH;

    __shared__ float As[BKD][BM + 4];
    __shared__ float Bs[BKD][BN];

    const int tid = threadIdx.x;
    const int tx = tid & 15, ty = tid >> 4;
    float acc[8][8];
#pragma unroll
    for (int i = 0; i < 8; i++)
#pragma unroll
        for (int j = 0; j < 8; j++) acc[i][j] = 0.f;

    for (int k0 = 0; k0 < II; k0 += BKD) {
#pragma unroll
        for (int l = 0; l < 2; l++) {
            int idx = tid + l * 256;
            int m = idx >> 2, c4 = (idx & 3) * 4;
            int mc = (m < rows) ? m : (rows - 1);
            float4 v = *(const float4*)&g_h[(size_t)(row0 + mc) * II + k0 + c4];
            As[c4 + 0][m] = v.x; As[c4 + 1][m] = v.y;
            As[c4 + 2][m] = v.z; As[c4 + 3][m] = v.w;
        }
#pragma unroll
        for (int l = 0; l < 2; l++) {
            int idx = tid + l * 256;
            int kk = idx >> 5, n4 = (idx & 31) * 4;
            *(float4*)&Bs[kk][n4] =
                *(const float4*)&Bp[(size_t)(k0 + kk) * HH + n0 + n4];
        }
        __syncthreads();
#pragma unroll
        for (int kk = 0; kk < BKD; kk++) {
            float a[8], b[8];
#pragma unroll
            for (int i = 0; i < 4; i++) {
                a[i]     = As[kk][ty * 4 + i];
                a[4 + i] = As[kk][64 + ty * 4 + i];
            }
#pragma unroll
            for (int j = 0; j < 4; j++) {
                b[j]     = Bs[kk][tx * 4 + j];
                b[4 + j] = Bs[kk][64 + tx * 4 + j];
            }
#pragma unroll
            for (int i = 0; i < 8; i++)
#pragma unroll
                for (int j = 0; j < 8; j++)
                    acc[i][j] = fmaf(a[i], b[j], acc[i][j]);
        }
        __syncthreads();
    }

#pragma unroll
    for (int i = 0; i < 8; i++) {
        int m = (i < 4) ? (ty * 4 + i) : (64 + ty * 4 + i - 4);
        if (m >= rows) continue;
        float w = g_rw[row0 + m];
        size_t base = (size_t)(row0 + m) * HH + n0;
#pragma unroll
        for (int jh = 0; jh < 2; jh++) {
            float4 v;
            v.x = acc[i][jh * 4 + 0] * w;
            v.y = acc[i][jh * 4 + 1] * w;
            v.z = acc[i][jh * 4 + 2] * w;
            v.w = acc[i][jh * 4 + 3] * w;
            *(float4*)&g_out[base + (jh == 0 ? tx * 4 : 64 + tx * 4)] = v;
        }
    }
}

// ---------------------------------------------------------------------------
// Combine: y[t] = out[pos(t,0)] + out[pos(t,1)]  (weights already applied)
__global__ void combine_kernel(float* __restrict__ y) {
    int idx = blockIdx.x * blockDim.x + threadIdx.x;   // T*H/4 threads
    int t  = idx >> 9;           // H/4 = 512 float4 per token
    int c4 = idx & 511;
    const float4* o = (const float4*)g_out;
    int p0 = g_pos[t * 2], p1 = g_pos[t * 2 + 1];
    float4 v0 = o[(size_t)p0 * 512 + c4];
    float4 v1 = o[(size_t)p1 * 512 + c4];
    float4 r;
    r.x = v0.x + v1.x; r.y = v0.y + v1.y;
    r.z = v0.z + v1.z; r.w = v0.w + v1.w;
    ((float4*)y)[idx] = r;
}

// ---------------------------------------------------------------------------
extern "C" void kernel_launch(void* const* d_in, const int* in_sizes, int n_in,
                              void* d_out, int out_size) {
    const float* x  = (const float*)d_in[0];
    const float* rw = (const float*)d_in[1];
    const float* w1 = (const float*)d_in[2];
    const float* w2 = (const float*)d_in[3];
    float* y = (float*)d_out;

    init_kernel<<<1, 32>>>();
    router_kernel<<<TT / 8, 256>>>(x, rw);
    build_kernel<<<1, 32>>>(y, (long long)out_size);
    scatter_kernel<<<TK / 256, 256>>>();
    dim3 g1(II / BN, 136);
    gemm1_kernel<<<g1, 256>>>(x, w1);
    dim3 g2(HH / BN, 136);
    gemm2_kernel<<<g2, 256>>>(w2);
    combine_kernel<<<(TT * HH / 4) / 256, 256>>>(y);
}

// round 2
// speedup vs baseline: 1.0021x; 1.0021x over previous
#include <cuda_runtime.h>

// Problem constants
#define TT   8192           // tokens = B*S
#define HH   2048           // hidden
#define II   4096           // intermediate
#define EE   8              // experts
#define TK   (TT*2)         // dispatched rows (top-2)
#define BM   128
#define BN   128
#define BKD  16
#define MAXTILES 144        // worst case: 128 full tiles + 7 remainders

// Scratch (device globals: allocation-free rule)
__device__ float g_h[(size_t)TK * II];      // 256 MB: GEMM1 output
__device__ float g_out[(size_t)TK * HH];    // 128 MB: GEMM2 output (weighted)
__device__ int   g_topi[TK];
__device__ float g_topw[TK];
__device__ int   g_rowtok[TK];
__device__ float g_rw[TK];
__device__ int   g_pos[TK];
__device__ int   g_counts[EE];
__device__ int   g_offsets[EE + 1];
__device__ int   g_fill[EE];
__device__ int   g_tile_e[MAXTILES];
__device__ int   g_tile_row[MAXTILES];
__device__ int   g_tile_rows[MAXTILES];
__device__ int   g_num_tiles;

// ---------------------------------------------------------------------------
__global__ void init_kernel() {
    int t = threadIdx.x;
    if (t < EE) { g_counts[t] = 0; g_fill[t] = 0; }
    if (t == 0) g_num_tiles = 0;
}

// ---------------------------------------------------------------------------
// Router: one warp per token. 8 expert dots over H=2048, fp32 softmax, top-2.
__global__ void router_kernel(const float* __restrict__ x,
                              const float* __restrict__ rw) {
    int warp = (blockIdx.x * blockDim.x + threadIdx.x) >> 5;
    int lane = threadIdx.x & 31;
    if (warp >= TT) return;
    const float* xr = x + (size_t)warp * HH;
    float acc[EE];
#pragma unroll
    for (int e = 0; e < EE; e++) acc[e] = 0.f;
    for (int i = lane * 4; i < HH; i += 128) {
        float4 xv = *(const float4*)&xr[i];
#pragma unroll
        for (int e = 0; e < EE; e++) {
            float4 wv = *(const float4*)&rw[e * HH + i];
            acc[e] += xv.x * wv.x + xv.y * wv.y + xv.z * wv.z + xv.w * wv.w;
        }
    }
#pragma unroll
    for (int e = 0; e < EE; e++)
#pragma unroll
        for (int off = 16; off; off >>= 1)
            acc[e] += __shfl_xor_sync(0xffffffffu, acc[e], off);

    if (lane == 0) {
        float mx = acc[0];
#pragma unroll
        for (int e = 1; e < EE; e++) mx = fmaxf(mx, acc[e]);
        float p[EE], s = 0.f;
#pragma unroll
        for (int e = 0; e < EE; e++) { p[e] = expf(acc[e] - mx); s += p[e]; }
        float inv = 1.f / s;
        int i1 = 0; float v1 = p[0];
#pragma unroll
        for (int e = 1; e < EE; e++) if (p[e] > v1) { v1 = p[e]; i1 = e; }
        int i2 = -1; float v2 = -1.f;
#pragma unroll
        for (int e = 0; e < EE; e++)
            if (e != i1 && p[e] > v2) { v2 = p[e]; i2 = e; }
        g_topi[warp * 2]     = i1; g_topw[warp * 2]     = v1 * inv;
        g_topi[warp * 2 + 1] = i2; g_topw[warp * 2 + 1] = v2 * inv;
        atomicAdd(&g_counts[i1], 1);
        atomicAdd(&g_counts[i2], 1);
    }
}

// ---------------------------------------------------------------------------
// Offsets + tile metadata (tiny serial work). Also writes tokens_per_expert
// tail of d_out if out_size > T*H, and zero-fills any remaining tail.
__global__ void build_kernel(float* d_out, long long out_size) {
    if (threadIdx.x != 0) return;
    int off = 0;
    for (int e = 0; e < EE; e++) { g_offsets[e] = off; off += g_counts[e]; }
    g_offsets[EE] = off;
    int nt = 0;
    for (int e = 0; e < EE; e++) {
        int n = g_counts[e];
        for (int j = 0; j < n; j += BM) {
            g_tile_e[nt]    = e;
            g_tile_row[nt]  = g_offsets[e] + j;
            g_tile_rows[nt] = (n - j < BM) ? (n - j) : BM;
            nt++;
        }
    }
    g_num_tiles = nt;
    long long base = (long long)TT * HH;
    long long extra = out_size - base;
    for (long long i = 0; i < extra; i++)
        d_out[base + i] = (i < EE) ? (float)g_counts[i] : 0.f;
}

// ---------------------------------------------------------------------------
// Scatter dispatched rows into expert-sorted order (unstable within expert;
// valid because final combine is an order-independent per-token sum).
__global__ void scatter_kernel() {
    int i = blockIdx.x * blockDim.x + threadIdx.x;
    if (i >= TK) return;
    int e = g_topi[i];
    int p = g_offsets[e] + atomicAdd(&g_fill[e], 1);
    g_rowtok[p] = i >> 1;
    g_rw[p]     = g_topw[i];
    g_pos[i]    = p;
}

// ---------------------------------------------------------------------------
// GEMM1: h[r, :] = gelu_tanh( x[tok(r), :] @ w1[e]  )   [gathered A rows]
__global__ __launch_bounds__(256, 2)
void gemm1_kernel(const float* __restrict__ X, const float* __restrict__ W1) {
    int tile = blockIdx.y;
    if (tile >= g_num_tiles) return;
    const int e    = g_tile_e[tile];
    const int row0 = g_tile_row[tile];
    const int rows = g_tile_rows[tile];
    const int n0   = blockIdx.x * BN;
    const float* __restrict__ Bp = W1 + (size_t)e * HH * II;

    __shared__ float As[BKD][BM + 4];
    __shared__ float Bs[BKD][BN];
    __shared__ int   stok[BM];

    const int tid = threadIdx.x;
    if (tid < BM) {
        int mm = (tid < rows) ? tid : (rows - 1);
        stok[tid] = g_rowtok[row0 + mm];
    }
    __syncthreads();

    const int tx = tid & 15, ty = tid >> 4;
    float acc[8][8];
#pragma unroll
    for (int i = 0; i < 8; i++)
#pragma unroll
        for (int j = 0; j < 8; j++) acc[i][j] = 0.f;

    for (int k0 = 0; k0 < HH; k0 += BKD) {
#pragma unroll
        for (int l = 0; l < 2; l++) {
            int idx = tid + l * 256;
            int m = idx >> 2, c4 = (idx & 3) * 4;
            float4 v = *(const float4*)&X[(size_t)stok[m] * HH + k0 + c4];
            As[c4 + 0][m] = v.x; As[c4 + 1][m] = v.y;
            As[c4 + 2][m] = v.z; As[c4 + 3][m] = v.w;
        }
#pragma unroll
        for (int l = 0; l < 2; l++) {
            int idx = tid + l * 256;
            int kk = idx >> 5, n4 = (idx & 31) * 4;
            *(float4*)&Bs[kk][n4] =
                *(const float4*)&Bp[(size_t)(k0 + kk) * II + n0 + n4];
        }
        __syncthreads();
#pragma unroll
        for (int kk = 0; kk < BKD; kk++) {
            float a[8], b[8];
#pragma unroll
            for (int i = 0; i < 4; i++) {
                a[i]     = As[kk][ty * 4 + i];
                a[4 + i] = As[kk][64 + ty * 4 + i];
            }
#pragma unroll
            for (int j = 0; j < 4; j++) {
                b[j]     = Bs[kk][tx * 4 + j];
                b[4 + j] = Bs[kk][64 + tx * 4 + j];
            }
#pragma unroll
            for (int i = 0; i < 8; i++)
#pragma unroll
                for (int j = 0; j < 8; j++)
                    acc[i][j] = fmaf(a[i], b[j], acc[i][j]);
        }
        __syncthreads();
    }

    // epilogue: tanh-GELU + store
#pragma unroll
    for (int i = 0; i < 8; i++) {
        int m = (i < 4) ? (ty * 4 + i) : (64 + ty * 4 + i - 4);
        if (m >= rows) continue;
        size_t base = (size_t)(row0 + m) * II + n0;
#pragma unroll
        for (int jh = 0; jh < 2; jh++) {
            float4 v;
            float* pv = &v.x;
#pragma unroll
            for (int j = 0; j < 4; j++) {
                float z = acc[i][jh * 4 + j];
                float t = 0.7978845608028654f * (z + 0.044715f * z * z * z);
                pv[j] = 0.5f * z * (1.f + tanhf(t));
            }
            *(float4*)&g_h[base + (jh == 0 ? tx * 4 : 64 + tx * 4)] = v;
        }
    }
}

// ---------------------------------------------------------------------------
// GEMM2: out[r, :] = rw[r] * ( h[r, :] @ w2[e] )
__global__ __launch_bounds__(256, 2)
void gemm2_kernel(const float* __restrict__ W2) {
    int tile = blockIdx.y;
    if (tile >= g_num_tiles) return;
    const int e    = g_tile_e[tile];
    const int row0 = g_tile_row[tile];
    const int rows = g_tile_rows[tile];
    const int n0   = blockIdx.x * BN;
    const float* __restrict__ Bp = W2 + (size_t)e * II * HH;

    __shared__ float As[BKD][BM + 4];
    __shared__ float Bs[BKD][BN];

    const int tid = threadIdx.x;
    const int tx = tid & 15, ty = tid >> 4;
    float acc[8][8];
#pragma unroll
    for (int i = 0; i < 8; i++)
#pragma unroll
        for (int j = 0; j < 8; j++) acc[i][j] = 0.f;

    for (int k0 = 0; k0 < II; k0 += BKD) {
#pragma unroll
        for (int l = 0; l < 2; l++) {
            int idx = tid + l * 256;
            int m = idx >> 2, c4 = (idx & 3) * 4;
            int mc = (m < rows) ? m : (rows - 1);
            float4 v = *(const float4*)&g_h[(size_t)(row0 + mc) * II + k0 + c4];
            As[c4 + 0][m] = v.x; As[c4 + 1][m] = v.y;
            As[c4 + 2][m] = v.z; As[c4 + 3][m] = v.w;
        }
#pragma unroll
        for (int l = 0; l < 2; l++) {
            int idx = tid + l * 256;
            int kk = idx >> 5, n4 = (idx & 31) * 4;
            *(float4*)&Bs[kk][n4] =
                *(const float4*)&Bp[(size_t)(k0 + kk) * HH + n0 + n4];
        }
        __syncthreads();
#pragma unroll
        for (int kk = 0; kk < BKD; kk++) {
            float a[8], b[8];
#pragma unroll
            for (int i = 0; i < 4; i++) {
                a[i]     = As[kk][ty * 4 + i];
                a[4 + i] = As[kk][64 + ty * 4 + i];
            }
#pragma unroll
            for (int j = 0; j < 4; j++) {
                b[j]     = Bs[kk][tx * 4 + j];
                b[4 + j] = Bs[kk][64 + tx * 4 + j];
            }
#pragma unroll
            for (int i = 0; i < 8; i++)
#pragma unroll
                for (int j = 0; j < 8; j++)
                    acc[i][j] = fmaf(a[i], b[j], acc[i][j]);
        }
        __syncthreads();
    }

#pragma unroll
    for (int i = 0; i < 8; i++) {
        int m = (i < 4) ? (ty * 4 + i) : (64 + ty * 4 + i - 4);
        if (m >= rows) continue;
        float w = g_rw[row0 + m];
        size_t base = (size_t)(row0 + m) * HH + n0;
#pragma unroll
        for (int jh = 0; jh < 2; jh++) {
            float4 v;
            v.x = acc[i][jh * 4 + 0] * w;
            v.y = acc[i][jh * 4 + 1] * w;
            v.z = acc[i][jh * 4 + 2] * w;
            v.w = acc[i][jh * 4 + 3] * w;
            *(float4*)&g_out[base + (jh == 0 ? tx * 4 : 64 + tx * 4)] = v;
        }
    }
}

// ---------------------------------------------------------------------------
// Combine: y[t] = out[pos(t,0)] + out[pos(t,1)]  (weights already applied)
__global__ void combine_kernel(float* __restrict__ y) {
    int idx = blockIdx.x * blockDim.x + threadIdx.x;   // T*H/4 threads
    int t  = idx >> 9;           // H/4 = 512 float4 per token
    int c4 = idx & 511;
    const float4* o = (const float4*)g_out;
    int p0 = g_pos[t * 2], p1 = g_pos[t * 2 + 1];
    float4 v0 = o[(size_t)p0 * 512 + c4];
    float4 v1 = o[(size_t)p1 * 512 + c4];
    float4 r;
    r.x = v0.x + v1.x; r.y = v0.y + v1.y;
    r.z = v0.z + v1.z; r.w = v0.w + v1.w;
    ((float4*)y)[idx] = r;
}

// ---------------------------------------------------------------------------
extern "C" void kernel_launch(void* const* d_in, const int* in_sizes, int n_in,
                              void* d_out, int out_size) {
    const float* x  = (const float*)d_in[0];
    const float* rw = (const float*)d_in[1];
    const float* w1 = (const float*)d_in[2];
    const float* w2 = (const float*)d_in[3];
    float* y = (float*)d_out;

    init_kernel<<<1, 32>>>();
    router_kernel<<<TT / 8, 256>>>(x, rw);
    build_kernel<<<1, 32>>>(y, (long long)out_size);
    scatter_kernel<<<TK / 256, 256>>>();
    dim3 g1(II / BN, 136);
    gemm1_kernel<<<g1, 256>>>(x, w1);
    dim3 g2(HH / BN, 136);
    gemm2_kernel<<<g2, 256>>>(w2);
    combine_kernel<<<(TT * HH / 4) / 256, 256>>>(y);
}

// round 6
// speedup vs baseline: 2.3322x; 2.3273x over previous
#include <cuda_runtime.h>
#include <cuda_bf16.h>
#include <cstdint>

#define TT 8192
#define HH 2048
#define II 4096
#define EE 8
#define TK (TT*2)
#define MAXTILES 144
#define BK 16

// ---- pool (402.9MB total statics; 403MB proven working in R1) ----
#define OFF_HH  0ULL                 // h hi  bf16 [TK][II]   134MB
#define OFF_HL  134217728ULL         // h lo  bf16 [TK][II]   134MB
#define OFF_X   268435456ULL         // x hi  bf16 [TT][HH]    32MB (dead after GEMM1)
#define OFF_XL  301989888ULL         // x lo  bf16 [TT][HH]    32MB
#define OFF_OUT 268435456ULL         // out  fp32 [TK][HH]    134MB (reuses x region)
#define POOL_BYTES 402653184ULL

__device__ char g_pool[POOL_BYTES];
__device__ int   g_topi[TK];
__device__ float g_topw[TK];
__device__ int   g_rowtok[TK];
__device__ float g_rw[TK];
__device__ int   g_pos[TK];
__device__ int   g_counts[EE];
__device__ int   g_offsets[EE + 1];
__device__ int   g_fill[EE];
__device__ int   g_tile_e[MAXTILES];
__device__ int   g_tile_row[MAXTILES];
__device__ int   g_tile_rows[MAXTILES];
__device__ int   g_num_tiles;

// ---- smem layout inside GEMM kernel (static, 41984B + abase) ----
// A stages:  s*8192 (Ah 4096 | Al 4096), s=0,1      -> [0, 16384)
// B fp32 staging: 16 rows x 512B                    -> [16384, 24576)
// Bh stages: 24576 + s*4352  (16 rows x 272B pitch) -> [24576, 33280)
// Bl stages: 33280 + s*4352                         -> [33280, 41984)
#define BSTG_OFF 16384
#define BH_OFF   24576
#define BL_OFF   33280
#define BPITCH   272

// ---------------- PTX helpers (sm_80 baseline ISA) ----------------
__device__ __forceinline__ uint32_t smem_u32(const void* p) {
    uint32_t a;
    asm("{ .reg .u64 t; cvta.to.shared.u64 t, %1; cvt.u32.u64 %0, t; }"
        : "=r"(a) : "l"(p));
    return a;
}
__device__ __forceinline__ void cpasync16(uint32_t dst, const void* src) {
    asm volatile("cp.async.cg.shared.global [%0], [%1], 16;"
                 :: "r"(dst), "l"(src) : "memory");
}
__device__ __forceinline__ void ldmx4(uint32_t* r, uint32_t addr) {
    asm volatile("ldmatrix.sync.aligned.m8n8.x4.shared.b16 {%0,%1,%2,%3}, [%4];"
                 : "=r"(r[0]), "=r"(r[1]), "=r"(r[2]), "=r"(r[3]) : "r"(addr));
}
__device__ __forceinline__ void ldmx4t(uint32_t* r, uint32_t addr) {
    asm volatile("ldmatrix.sync.aligned.m8n8.x4.trans.shared.b16 {%0,%1,%2,%3}, [%4];"
                 : "=r"(r[0]), "=r"(r[1]), "=r"(r[2]), "=r"(r[3]) : "r"(addr));
}
__device__ __forceinline__ void mma16816(float* d, const uint32_t* a,
                                         const uint32_t* b) {
    asm volatile(
        "mma.sync.aligned.m16n8k16.row.col.f32.bf16.bf16.f32 "
        "{%0,%1,%2,%3}, {%4,%5,%6,%7}, {%8,%9}, {%0,%1,%2,%3};"
        : "+f"(d[0]), "+f"(d[1]), "+f"(d[2]), "+f"(d[3])
        : "r"(a[0]), "r"(a[1]), "r"(a[2]), "r"(a[3]), "r"(b[0]), "r"(b[1]));
}

// ---------------- small kernels (proven in R1) ----------------
__global__ void init_kernel() {
    int t = threadIdx.x;
    if (t < EE) { g_counts[t] = 0; g_fill[t] = 0; }
    if (t == 0) g_num_tiles = 0;
}

__global__ void router_kernel(const float* __restrict__ x,
                              const float* __restrict__ rw) {
    int warp = (blockIdx.x * blockDim.x + threadIdx.x) >> 5;
    int lane = threadIdx.x & 31;
    if (warp >= TT) return;
    const float* xr = x + (size_t)warp * HH;
    float acc[EE];
#pragma unroll
    for (int e = 0; e < EE; e++) acc[e] = 0.f;
    for (int i = lane * 4; i < HH; i += 128) {
        float4 xv = *(const float4*)&xr[i];
#pragma unroll
        for (int e = 0; e < EE; e++) {
            float4 wv = *(const float4*)&rw[e * HH + i];
            acc[e] += xv.x * wv.x + xv.y * wv.y + xv.z * wv.z + xv.w * wv.w;
        }
    }
#pragma unroll
    for (int e = 0; e < EE; e++)
#pragma unroll
        for (int off = 16; off; off >>= 1)
            acc[e] += __shfl_xor_sync(0xffffffffu, acc[e], off);
    if (lane == 0) {
        float mx = acc[0];
#pragma unroll
        for (int e = 1; e < EE; e++) mx = fmaxf(mx, acc[e]);
        float p[EE], s = 0.f;
#pragma unroll
        for (int e = 0; e < EE; e++) { p[e] = expf(acc[e] - mx); s += p[e]; }
        float inv = 1.f / s;
        int i1 = 0; float v1 = p[0];
#pragma unroll
        for (int e = 1; e < EE; e++) if (p[e] > v1) { v1 = p[e]; i1 = e; }
        int i2 = -1; float v2 = -1.f;
#pragma unroll
        for (int e = 0; e < EE; e++)
            if (e != i1 && p[e] > v2) { v2 = p[e]; i2 = e; }
        g_topi[warp * 2]     = i1; g_topw[warp * 2]     = v1 * inv;
        g_topi[warp * 2 + 1] = i2; g_topw[warp * 2 + 1] = v2 * inv;
        atomicAdd(&g_counts[i1], 1);
        atomicAdd(&g_counts[i2], 1);
    }
}

__global__ void build_kernel(float* d_out, long long out_size) {
    if (threadIdx.x != 0) return;
    int off = 0;
    for (int e = 0; e < EE; e++) { g_offsets[e] = off; off += g_counts[e]; }
    g_offsets[EE] = off;
    int nt = 0;
    for (int e = 0; e < EE; e++) {
        int n = g_counts[e];
        for (int j = 0; j < n; j += 128) {
            g_tile_e[nt]    = e;
            g_tile_row[nt]  = g_offsets[e] + j;
            g_tile_rows[nt] = (n - j < 128) ? (n - j) : 128;
            nt++;
        }
    }
    g_num_tiles = nt;
    long long base = (long long)TT * HH;
    long long extra = out_size - base;
    for (long long i = 0; i < extra; i++)
        d_out[base + i] = (i < EE) ? (float)g_counts[i] : 0.f;
}

__global__ void scatter_kernel() {
    int i = blockIdx.x * blockDim.x + threadIdx.x;
    if (i >= TK) return;
    int e = g_topi[i];
    int p = g_offsets[e] + atomicAdd(&g_fill[e], 1);
    g_rowtok[p] = i >> 1;
    g_rw[p]     = g_topw[i];
    g_pos[i]    = p;
}

// ---------------- x -> bf16 hi/lo split ----------------
__global__ void convert_x_kernel(const float* __restrict__ x) {
    int i = blockIdx.x * blockDim.x + threadIdx.x;    // < TT*HH/4
    float4 v = ((const float4*)x)[i];
    __nv_bfloat162 h0, h1, l0, l1;
    h0.x = __float2bfloat16(v.x); l0.x = __float2bfloat16(v.x - __bfloat162float(h0.x));
    h0.y = __float2bfloat16(v.y); l0.y = __float2bfloat16(v.y - __bfloat162float(h0.y));
    h1.x = __float2bfloat16(v.z); l1.x = __float2bfloat16(v.z - __bfloat162float(h1.x));
    h1.y = __float2bfloat16(v.w); l1.y = __float2bfloat16(v.w - __bfloat162float(h1.y));
    __nv_bfloat162* oh = (__nv_bfloat162*)(g_pool + OFF_X);
    __nv_bfloat162* ol = (__nv_bfloat162*)(g_pool + OFF_XL);
    oh[i * 2] = h0; oh[i * 2 + 1] = h1;
    ol[i * 2] = l0; ol[i * 2 + 1] = l1;
}

// ---------------- grouped GEMM: mma.sync bf16x3, on-the-fly B split --------
// MODE 0: h = gelu(xs @ w1), A = x hi/lo (gathered), B = w1 [E][HH][II] fp32
// MODE 1: out = rw*(h @ w2), A = h hi/lo,            B = w2 [E][II][HH] fp32
template <int MODE>
__global__ __launch_bounds__(256) void moe_mma_kernel(const float* __restrict__ W) {
    const int KLEN = MODE ? II : HH;     // K
    const int BROW = MODE ? HH : II;     // B row length (full N)
    const int NC = KLEN / BK;
    int tile = blockIdx.y;
    if (tile >= g_num_tiles) return;
    const int e = g_tile_e[tile], row0 = g_tile_row[tile], rows = g_tile_rows[tile];
    const int n0 = blockIdx.x * 128;
    const int tid = threadIdx.x, wid = tid >> 5, lane = tid & 31;
    const int wm = wid & 1, wn = wid >> 1;     // warp tile 64(m) x 32(n)

    __shared__ __align__(128) char SM[41984];
    __shared__ int abase_s[128];
    uint32_t sb = smem_u32(SM);

    const __nv_bfloat16* Ahg = (const __nv_bfloat16*)(g_pool + (MODE ? OFF_HH : OFF_X));
    const __nv_bfloat16* Alg = (const __nv_bfloat16*)(g_pool + (MODE ? OFF_HL : OFF_XL));
    const float* We = W + (size_t)e * KLEN * BROW;

    if (tid < 128) {
        int mc = (tid < rows) ? tid : (rows - 1);
        abase_s[tid] = (MODE == 0) ? g_rowtok[row0 + mc] * HH : (row0 + mc) * II;
    }
    __syncthreads();

    const int lrow = tid >> 1, lc = tid & 1;
    auto load_chunk = [&](int st, int k0) {
        // A hi/lo bf16: 128 rows x 32B
        uint32_t so = sb + (uint32_t)(st * 8192 + lrow * 32 + lc * 16);
        size_t ae = (size_t)abase_s[lrow] + k0 + lc * 8;
        cpasync16(so,        (const char*)Ahg + ae * 2);
        cpasync16(so + 4096, (const char*)Alg + ae * 2);
        // B fp32 staging: 16 rows x 512B
#pragma unroll
        for (int j = 0; j < 2; j++) {
            int seg = tid + j * 256;
            int r = seg >> 5, o16 = seg & 31;
            uint32_t bd = sb + (uint32_t)(BSTG_OFF + r * 512 + o16 * 16);
            const char* src = (const char*)(We + (size_t)(k0 + r) * BROW + n0) + o16 * 16;
            cpasync16(bd, src);
        }
    };

    float acc[4][4][4];
#pragma unroll
    for (int a = 0; a < 4; a++)
#pragma unroll
        for (int b = 0; b < 4; b++)
#pragma unroll
            for (int c = 0; c < 4; c++) acc[a][b][c] = 0.f;

    load_chunk(0, 0);
    asm volatile("cp.async.commit_group;" ::: "memory");

    for (int ch = 0; ch < NC; ch++) {
        int st = ch & 1;
        asm volatile("cp.async.wait_group 0;" ::: "memory");
        __syncthreads();

        // convert B staging fp32 -> Bh/Bl bf16 (thread t: k=t>>4, n=(t&15)*8)
        {
            int k = tid >> 4, n = (tid & 15) * 8;
            const float4* src = (const float4*)(SM + BSTG_OFF + k * 512 + n * 4);
            float4 v0 = src[0], v1 = src[1];
            float vs[8] = {v0.x, v0.y, v0.z, v0.w, v1.x, v1.y, v1.z, v1.w};
            __align__(16) __nv_bfloat16 hb[8], lb[8];
#pragma unroll
            for (int i = 0; i < 8; i++) {
                hb[i] = __float2bfloat16(vs[i]);
                lb[i] = __float2bfloat16(vs[i] - __bfloat162float(hb[i]));
            }
            *(uint4*)(SM + BH_OFF + st * 4352 + k * BPITCH + n * 2) = *(uint4*)hb;
            *(uint4*)(SM + BL_OFF + st * 4352 + k * BPITCH + n * 2) = *(uint4*)lb;
        }
        __syncthreads();

        if (ch + 1 < NC) load_chunk(st ^ 1, (ch + 1) * BK);
        asm volatile("cp.async.commit_group;" ::: "memory");

        // fragments
        uint32_t Afh[4][4], Afl[4][4], Bfh[8], Bfl[8];
#pragma unroll
        for (int mi = 0; mi < 4; mi++) {
            uint32_t ad = sb + (uint32_t)(st * 8192 +
                (wm * 64 + mi * 16 + (lane & 15)) * 32 + ((lane >> 4) & 1) * 16);
            ldmx4(Afh[mi], ad);
            ldmx4(Afl[mi], ad + 4096);
        }
#pragma unroll
        for (int np = 0; np < 2; np++) {
            int krow = ((lane >> 3) & 1) * 8 + (lane & 7);
            int ncol = wn * 32 + np * 16 + ((lane >> 4) & 1) * 8;
            uint32_t bd = sb + (uint32_t)(BH_OFF + st * 4352 + krow * BPITCH + ncol * 2);
            ldmx4t(&Bfh[np * 4], bd);
            ldmx4t(&Bfl[np * 4], bd + 8704);      // BL_OFF - BH_OFF
        }
#pragma unroll
        for (int mi = 0; mi < 4; mi++)
#pragma unroll
            for (int ni = 0; ni < 4; ni++) {
                mma16816(acc[mi][ni], Afh[mi], &Bfh[ni * 2]);
                mma16816(acc[mi][ni], Afl[mi], &Bfh[ni * 2]);
                mma16816(acc[mi][ni], Afh[mi], &Bfl[ni * 2]);
            }
    }

    // ---------------- epilogue ----------------
    __nv_bfloat16* hh = (__nv_bfloat16*)(g_pool + OFF_HH);
    __nv_bfloat16* hl = (__nv_bfloat16*)(g_pool + OFF_HL);
    float* outp = (float*)(g_pool + OFF_OUT);
#pragma unroll
    for (int mi = 0; mi < 4; mi++) {
#pragma unroll
        for (int hr = 0; hr < 2; hr++) {
            int mloc = wm * 64 + mi * 16 + hr * 8 + (lane >> 2);
            if (mloc >= rows) continue;
            if (MODE == 0) {
                size_t base = (size_t)(row0 + mloc) * II + n0 + wn * 32 + (lane & 3) * 2;
#pragma unroll
                for (int ni = 0; ni < 4; ni++) {
                    float v0 = acc[mi][ni][hr * 2 + 0];
                    float v1 = acc[mi][ni][hr * 2 + 1];
                    float t0 = 0.7978845608028654f * (v0 + 0.044715f * v0 * v0 * v0);
                    float t1 = 0.7978845608028654f * (v1 + 0.044715f * v1 * v1 * v1);
                    float g0 = 0.5f * v0 * (1.f + tanhf(t0));
                    float g1 = 0.5f * v1 * (1.f + tanhf(t1));
                    __nv_bfloat162 h, l;
                    h.x = __float2bfloat16(g0);
                    l.x = __float2bfloat16(g0 - __bfloat162float(h.x));
                    h.y = __float2bfloat16(g1);
                    l.y = __float2bfloat16(g1 - __bfloat162float(h.y));
                    *(__nv_bfloat162*)&hh[base + ni * 8] = h;
                    *(__nv_bfloat162*)&hl[base + ni * 8] = l;
                }
            } else {
                float w = g_rw[row0 + mloc];
                size_t base = (size_t)(row0 + mloc) * HH + n0 + wn * 32 + (lane & 3) * 2;
#pragma unroll
                for (int ni = 0; ni < 4; ni++) {
                    float2 o;
                    o.x = acc[mi][ni][hr * 2 + 0] * w;
                    o.y = acc[mi][ni][hr * 2 + 1] * w;
                    *(float2*)&outp[base + ni * 8] = o;
                }
            }
        }
    }
}

// ---------------- combine ----------------
__global__ void combine_kernel(float* __restrict__ y) {
    int idx = blockIdx.x * blockDim.x + threadIdx.x;
    int t = idx >> 9, c4 = idx & 511;
    const float4* o = (const float4*)(g_pool + OFF_OUT);
    int p0 = g_pos[t * 2], p1 = g_pos[t * 2 + 1];
    float4 v0 = o[(size_t)p0 * 512 + c4];
    float4 v1 = o[(size_t)p1 * 512 + c4];
    float4 r;
    r.x = v0.x + v1.x; r.y = v0.y + v1.y;
    r.z = v0.z + v1.z; r.w = v0.w + v1.w;
    ((float4*)y)[idx] = r;
}

// ---------------- launch ----------------
extern "C" void kernel_launch(void* const* d_in, const int* in_sizes, int n_in,
                              void* d_out, int out_size) {
    const float* x  = (const float*)d_in[0];
    const float* rw = (const float*)d_in[1];
    const float* w1 = (const float*)d_in[2];
    const float* w2 = (const float*)d_in[3];
    float* y = (float*)d_out;

    init_kernel<<<1, 32>>>();
    router_kernel<<<TT / 8, 256>>>(x, rw);
    build_kernel<<<1, 32>>>(y, (long long)out_size);
    scatter_kernel<<<TK / 256, 256>>>();
    convert_x_kernel<<<(TT * HH / 4) / 256, 256>>>(x);

    moe_mma_kernel<0><<<dim3(II / 128, 136), 256>>>(w1);
    moe_mma_kernel<1><<<dim3(HH / 128, 136), 256>>>(w2);

    combine_kernel<<<(TT * HH / 4) / 256, 256>>>(y);
}

// round 7
// speedup vs baseline: 2.3978x; 1.0282x over previous
#include <cuda_runtime.h>
#include <cuda_bf16.h>
#include <cstdint>

#define TT 8192
#define HH 2048
#define II 4096
#define EE 8
#define TK (TT*2)
#define MAXTILES 144
#define BK 16

// ---- pool (402.9MB statics; >~900MB breaks module load — R4/R5 lesson) ----
#define OFF_HH  0ULL                 // h hi  bf16 [TK][II]   134MB
#define OFF_HL  134217728ULL         // h lo  bf16 [TK][II]   134MB
#define OFF_X   268435456ULL         // x hi  bf16 [TT][HH]    32MB (dead after GEMM1)
#define OFF_XL  301989888ULL         // x lo  bf16 [TT][HH]    32MB
#define OFF_OUT 268435456ULL         // out  fp32 [TK][HH]    134MB (reuses x region)
#define POOL_BYTES 402653184ULL

__device__ char g_pool[POOL_BYTES];
__device__ int   g_topi[TK];
__device__ float g_topw[TK];
__device__ int   g_rowtok[TK];
__device__ float g_rw[TK];
__device__ int   g_pos[TK];
__device__ int   g_counts[EE];
__device__ int   g_offsets[EE + 1];
__device__ int   g_fill[EE];
__device__ int   g_tile_e[MAXTILES];
__device__ int   g_tile_row[MAXTILES];
__device__ int   g_tile_rows[MAXTILES];
__device__ int   g_num_tiles;

#define BPITCH 272    // bf16 B row pitch bytes (136 bf16 >= 128, conflict-skewed)

// ---------------- PTX helpers (sm_80 baseline ISA) ----------------
__device__ __forceinline__ uint32_t smem_u32(const void* p) {
    uint32_t a;
    asm("{ .reg .u64 t; cvta.to.shared.u64 t, %1; cvt.u32.u64 %0, t; }"
        : "=r"(a) : "l"(p));
    return a;
}
__device__ __forceinline__ void cpasync16(uint32_t dst, const void* src) {
    asm volatile("cp.async.cg.shared.global [%0], [%1], 16;"
                 :: "r"(dst), "l"(src) : "memory");
}
__device__ __forceinline__ void ldmx4(uint32_t* r, uint32_t addr) {
    asm volatile("ldmatrix.sync.aligned.m8n8.x4.shared.b16 {%0,%1,%2,%3}, [%4];"
                 : "=r"(r[0]), "=r"(r[1]), "=r"(r[2]), "=r"(r[3]) : "r"(addr));
}
__device__ __forceinline__ void ldmx4t(uint32_t* r, uint32_t addr) {
    asm volatile("ldmatrix.sync.aligned.m8n8.x4.trans.shared.b16 {%0,%1,%2,%3}, [%4];"
                 : "=r"(r[0]), "=r"(r[1]), "=r"(r[2]), "=r"(r[3]) : "r"(addr));
}
__device__ __forceinline__ void mma16816(float* d, const uint32_t* a,
                                         const uint32_t* b) {
    asm volatile(
        "mma.sync.aligned.m16n8k16.row.col.f32.bf16.bf16.f32 "
        "{%0,%1,%2,%3}, {%4,%5,%6,%7}, {%8,%9}, {%0,%1,%2,%3};"
        : "+f"(d[0]), "+f"(d[1]), "+f"(d[2]), "+f"(d[3])
        : "r"(a[0]), "r"(a[1]), "r"(a[2]), "r"(a[3]), "r"(b[0]), "r"(b[1]));
}

// ---------------- small kernels (proven) ----------------
__global__ void init_kernel() {
    int t = threadIdx.x;
    if (t < EE) { g_counts[t] = 0; g_fill[t] = 0; }
    if (t == 0) g_num_tiles = 0;
}

__global__ void router_kernel(const float* __restrict__ x,
                              const float* __restrict__ rw) {
    int warp = (blockIdx.x * blockDim.x + threadIdx.x) >> 5;
    int lane = threadIdx.x & 31;
    if (warp >= TT) return;
    const float* xr = x + (size_t)warp * HH;
    float acc[EE];
#pragma unroll
    for (int e = 0; e < EE; e++) acc[e] = 0.f;
    for (int i = lane * 4; i < HH; i += 128) {
        float4 xv = *(const float4*)&xr[i];
#pragma unroll
        for (int e = 0; e < EE; e++) {
            float4 wv = *(const float4*)&rw[e * HH + i];
            acc[e] += xv.x * wv.x + xv.y * wv.y + xv.z * wv.z + xv.w * wv.w;
        }
    }
#pragma unroll
    for (int e = 0; e < EE; e++)
#pragma unroll
        for (int off = 16; off; off >>= 1)
            acc[e] += __shfl_xor_sync(0xffffffffu, acc[e], off);
    if (lane == 0) {
        float mx = acc[0];
#pragma unroll
        for (int e = 1; e < EE; e++) mx = fmaxf(mx, acc[e]);
        float p[EE], s = 0.f;
#pragma unroll
        for (int e = 0; e < EE; e++) { p[e] = expf(acc[e] - mx); s += p[e]; }
        float inv = 1.f / s;
        int i1 = 0; float v1 = p[0];
#pragma unroll
        for (int e = 1; e < EE; e++) if (p[e] > v1) { v1 = p[e]; i1 = e; }
        int i2 = -1; float v2 = -1.f;
#pragma unroll
        for (int e = 0; e < EE; e++)
            if (e != i1 && p[e] > v2) { v2 = p[e]; i2 = e; }
        g_topi[warp * 2]     = i1; g_topw[warp * 2]     = v1 * inv;
        g_topi[warp * 2 + 1] = i2; g_topw[warp * 2 + 1] = v2 * inv;
        atomicAdd(&g_counts[i1], 1);
        atomicAdd(&g_counts[i2], 1);
    }
}

__global__ void build_kernel(float* d_out, long long out_size) {
    if (threadIdx.x != 0) return;
    int off = 0;
    for (int e = 0; e < EE; e++) { g_offsets[e] = off; off += g_counts[e]; }
    g_offsets[EE] = off;
    int nt = 0;
    for (int e = 0; e < EE; e++) {
        int n = g_counts[e];
        for (int j = 0; j < n; j += 128) {
            g_tile_e[nt]    = e;
            g_tile_row[nt]  = g_offsets[e] + j;
            g_tile_rows[nt] = (n - j < 128) ? (n - j) : 128;
            nt++;
        }
    }
    g_num_tiles = nt;
    long long base = (long long)TT * HH;
    long long extra = out_size - base;
    for (long long i = 0; i < extra; i++)
        d_out[base + i] = (i < EE) ? (float)g_counts[i] : 0.f;
}

__global__ void scatter_kernel() {
    int i = blockIdx.x * blockDim.x + threadIdx.x;
    if (i >= TK) return;
    int e = g_topi[i];
    int p = g_offsets[e] + atomicAdd(&g_fill[e], 1);
    g_rowtok[p] = i >> 1;
    g_rw[p]     = g_topw[i];
    g_pos[i]    = p;
}

// ---------------- x -> bf16 hi/lo split ----------------
__global__ void convert_x_kernel(const float* __restrict__ x) {
    int i = blockIdx.x * blockDim.x + threadIdx.x;
    float4 v = ((const float4*)x)[i];
    __nv_bfloat162 h0, h1, l0, l1;
    h0.x = __float2bfloat16(v.x); l0.x = __float2bfloat16(v.x - __bfloat162float(h0.x));
    h0.y = __float2bfloat16(v.y); l0.y = __float2bfloat16(v.y - __bfloat162float(h0.y));
    h1.x = __float2bfloat16(v.z); l1.x = __float2bfloat16(v.z - __bfloat162float(h1.x));
    h1.y = __float2bfloat16(v.w); l1.y = __float2bfloat16(v.w - __bfloat162float(h1.y));
    __nv_bfloat162* oh = (__nv_bfloat162*)(g_pool + OFF_X);
    __nv_bfloat162* ol = (__nv_bfloat162*)(g_pool + OFF_XL);
    oh[i * 2] = h0; oh[i * 2 + 1] = h1;
    ol[i * 2] = l0; ol[i * 2 + 1] = l1;
}

// ---------------- grouped GEMM: mma.sync bf16x3, reg-staged B --------------
// MODE 0: h = gelu(xs @ w1)   MODE 1: out = rw*(h @ w2)
template <int MODE>
__global__ __launch_bounds__(256, 2) void moe_mma_kernel(const float* __restrict__ W) {
    const int KLEN = MODE ? II : HH;
    const int BROW = MODE ? HH : II;
    const int NC = KLEN / BK;
    int tile = blockIdx.y;
    if (tile >= g_num_tiles) return;
    const int e = g_tile_e[tile], row0 = g_tile_row[tile], rows = g_tile_rows[tile];
    const int n0 = blockIdx.x * 128;
    const int tid = threadIdx.x, wid = tid >> 5, lane = tid & 31;
    const int wm = wid & 1, wn = wid >> 1;     // warp tile 64(m) x 32(n)

    // A: 2 stages x (Ah 4096 | Al 4096); B: 2 stages x (Bh 4352 | Bl 4352)
    __shared__ __align__(128) char A_sm[2][8192];
    __shared__ __align__(128) char B_sm[2][8704];
    __shared__ int abase_s[128];
    uint32_t sbA = smem_u32(A_sm);
    uint32_t sbB = smem_u32(B_sm);

    const __nv_bfloat16* Ahg = (const __nv_bfloat16*)(g_pool + (MODE ? OFF_HH : OFF_X));
    const __nv_bfloat16* Alg = (const __nv_bfloat16*)(g_pool + (MODE ? OFF_HL : OFF_XL));
    const float* We = W + (size_t)e * KLEN * BROW;

    if (tid < 128) {
        int mc = (tid < rows) ? tid : (rows - 1);
        abase_s[tid] = (MODE == 0) ? g_rowtok[row0 + mc] * HH : (row0 + mc) * II;
    }
    __syncthreads();

    const int lrow = tid >> 1, lc = tid & 1;
    auto load_A = [&](int st, int k0) {
        uint32_t so = sbA + (uint32_t)(st * 8192 + lrow * 32 + lc * 16);
        size_t ae = (size_t)abase_s[lrow] + k0 + lc * 8;
        cpasync16(so,        (const char*)Ahg + ae * 2);
        cpasync16(so + 4096, (const char*)Alg + ae * 2);
        asm volatile("cp.async.commit_group;" ::: "memory");
    };

    // B reg staging: thread t covers k=t>>4 (0..15), n=(t&15)*8 (8 floats)
    const int bk_r = tid >> 4, bn_r = (tid & 15) * 8;
    const float* Bsrc = We + (size_t)bk_r * BROW + n0 + bn_r;
    float4 br0, br1;
    auto ldg_B = [&](int k0) {
        const float4* s = (const float4*)(Bsrc + (size_t)k0 * BROW);
        br0 = s[0]; br1 = s[1];
    };
    auto sts_B = [&](int st) {
        float vs[8] = {br0.x, br0.y, br0.z, br0.w, br1.x, br1.y, br1.z, br1.w};
        __align__(16) __nv_bfloat16 hb[8], lb[8];
#pragma unroll
        for (int i = 0; i < 8; i++) {
            hb[i] = __float2bfloat16(vs[i]);
            lb[i] = __float2bfloat16(vs[i] - __bfloat162float(hb[i]));
        }
        uint32_t bd = sbB + (uint32_t)(st * 8704 + bk_r * BPITCH + bn_r * 2);
        *(uint4*)(B_sm[st] + bk_r * BPITCH + bn_r * 2) = *(uint4*)hb;
        *(uint4*)(B_sm[st] + 4352 + bk_r * BPITCH + bn_r * 2) = *(uint4*)lb;
        (void)bd;
    };

    float acc[4][4][4];
#pragma unroll
    for (int a = 0; a < 4; a++)
#pragma unroll
        for (int b = 0; b < 4; b++)
#pragma unroll
            for (int c = 0; c < 4; c++) acc[a][b][c] = 0.f;

    ldg_B(0);
    load_A(0, 0);

    for (int ch = 0; ch < NC; ch++) {
        int st = ch & 1;
        sts_B(st);                              // B(ch) regs -> smem stage st
        if (ch + 1 < NC) ldg_B((ch + 1) * BK);  // prefetch B(ch+1) into regs
        asm volatile("cp.async.wait_group 0;" ::: "memory");   // A(ch) resident
        __syncthreads();
        if (ch + 1 < NC) load_A(st ^ 1, (ch + 1) * BK);

        uint32_t Afh[4][4], Afl[4][4], Bfh[8], Bfl[8];
#pragma unroll
        for (int mi = 0; mi < 4; mi++) {
            uint32_t ad = sbA + (uint32_t)(st * 8192 +
                (wm * 64 + mi * 16 + (lane & 15)) * 32 + ((lane >> 4) & 1) * 16);
            ldmx4(Afh[mi], ad);
            ldmx4(Afl[mi], ad + 4096);
        }
#pragma unroll
        for (int np = 0; np < 2; np++) {
            int krow = ((lane >> 3) & 1) * 8 + (lane & 7);
            int ncol = wn * 32 + np * 16 + ((lane >> 4) & 1) * 8;
            uint32_t bd = sbB + (uint32_t)(st * 8704 + krow * BPITCH + ncol * 2);
            ldmx4t(&Bfh[np * 4], bd);
            ldmx4t(&Bfl[np * 4], bd + 4352);
        }
#pragma unroll
        for (int mi = 0; mi < 4; mi++)
#pragma unroll
            for (int ni = 0; ni < 4; ni++) {
                mma16816(acc[mi][ni], Afh[mi], &Bfh[ni * 2]);
                mma16816(acc[mi][ni], Afl[mi], &Bfh[ni * 2]);
                mma16816(acc[mi][ni], Afh[mi], &Bfl[ni * 2]);
            }
        __syncthreads();   // B stage st fully consumed before overwrite at ch+2
    }

    // ---------------- epilogue ----------------
    __nv_bfloat16* hh = (__nv_bfloat16*)(g_pool + OFF_HH);
    __nv_bfloat16* hl = (__nv_bfloat16*)(g_pool + OFF_HL);
    float* outp = (float*)(g_pool + OFF_OUT);
#pragma unroll
    for (int mi = 0; mi < 4; mi++) {
#pragma unroll
        for (int hr = 0; hr < 2; hr++) {
            int mloc = wm * 64 + mi * 16 + hr * 8 + (lane >> 2);
            if (mloc >= rows) continue;
            if (MODE == 0) {
                size_t base = (size_t)(row0 + mloc) * II + n0 + wn * 32 + (lane & 3) * 2;
#pragma unroll
                for (int ni = 0; ni < 4; ni++) {
                    float v0 = acc[mi][ni][hr * 2 + 0];
                    float v1 = acc[mi][ni][hr * 2 + 1];
                    float t0 = 0.7978845608028654f * (v0 + 0.044715f * v0 * v0 * v0);
                    float t1 = 0.7978845608028654f * (v1 + 0.044715f * v1 * v1 * v1);
                    float g0 = 0.5f * v0 * (1.f + tanhf(t0));
                    float g1 = 0.5f * v1 * (1.f + tanhf(t1));
                    __nv_bfloat162 h, l;
                    h.x = __float2bfloat16(g0);
                    l.x = __float2bfloat16(g0 - __bfloat162float(h.x));
                    h.y = __float2bfloat16(g1);
                    l.y = __float2bfloat16(g1 - __bfloat162float(h.y));
                    *(__nv_bfloat162*)&hh[base + ni * 8] = h;
                    *(__nv_bfloat162*)&hl[base + ni * 8] = l;
                }
            } else {
                float w = g_rw[row0 + mloc];
                size_t base = (size_t)(row0 + mloc) * HH + n0 + wn * 32 + (lane & 3) * 2;
#pragma unroll
                for (int ni = 0; ni < 4; ni++) {
                    float2 o;
                    o.x = acc[mi][ni][hr * 2 + 0] * w;
                    o.y = acc[mi][ni][hr * 2 + 1] * w;
                    *(float2*)&outp[base + ni * 8] = o;
                }
            }
        }
    }
}

// ---------------- combine ----------------
__global__ void combine_kernel(float* __restrict__ y) {
    int idx = blockIdx.x * blockDim.x + threadIdx.x;
    int t = idx >> 9, c4 = idx & 511;
    const float4* o = (const float4*)(g_pool + OFF_OUT);
    int p0 = g_pos[t * 2], p1 = g_pos[t * 2 + 1];
    float4 v0 = o[(size_t)p0 * 512 + c4];
    float4 v1 = o[(size_t)p1 * 512 + c4];
    float4 r;
    r.x = v0.x + v1.x; r.y = v0.y + v1.y;
    r.z = v0.z + v1.z; r.w = v0.w + v1.w;
    ((float4*)y)[idx] = r;
}

// ---------------- launch ----------------
extern "C" void kernel_launch(void* const* d_in, const int* in_sizes, int n_in,
                              void* d_out, int out_size) {
    const float* x  = (const float*)d_in[0];
    const float* rw = (const float*)d_in[1];
    const float* w1 = (const float*)d_in[2];
    const float* w2 = (const float*)d_in[3];
    float* y = (float*)d_out;

    init_kernel<<<1, 32>>>();
    router_kernel<<<TT / 8, 256>>>(x, rw);
    build_kernel<<<1, 32>>>(y, (long long)out_size);
    scatter_kernel<<<TK / 256, 256>>>();
    convert_x_kernel<<<(TT * HH / 4) / 256, 256>>>(x);

    moe_mma_kernel<0><<<dim3(II / 128, 136), 256>>>(w1);
    moe_mma_kernel<1><<<dim3(HH / 128, 136), 256>>>(w2);

    combine_kernel<<<(TT * HH / 4) / 256, 256>>>(y);
}